// round 1
// baseline (speedup 1.0000x reference)
#include <cuda_runtime.h>
#include <math.h>

#define Bn 32
#define Sn 512
#define Hn 768
#define FDn 64
#define Pn 30
#define PPn 32           // padded P
#define NROWS (Bn*Sn)    // 16384

// ------------------ scratch (device globals; no allocations) ------------------
__device__ float g_text[NROWS * PPn];   // raw text projection, padded
__device__ float g_audio[NROWS * PPn];  // audio projection, padded
__device__ float g_part[512];           // block partial sums of text^2
__device__ float g_scale[1];            // 1/sqrt(sum text^2) == 1/norm^2
__device__ float g_raw0[Bn * Sn];       // fusion_att_raw at s=0 (pre-relu)
__device__ float g_fus0[Bn * Hn];       // fusion_data at s=0

// ------------------ K1: projections + sumsq partials ------------------
// grid 512, block 256. thread = (p=lane, rows wq+8*rr), 4 rows each.
__global__ __launch_bounds__(256) void k_proj(const float* __restrict__ hs,
                                              const float* __restrict__ ad,
                                              const float* __restrict__ Wt,
                                              const float* __restrict__ Wa) {
    __shared__ float red[256];
    int tid  = threadIdx.x;
    int lane = tid & 31;
    int wq   = tid >> 5;           // 0..7
    int row0 = blockIdx.x * 32;
    bool act = (lane < Pn);
    const float4* wt4 = (const float4*)(Wt + (act ? lane : 0) * Hn);
    const float4* wa4 = (const float4*)(Wa + (act ? lane : 0) * FDn);
    float sumsq = 0.f;

    for (int rr = 0; rr < 4; rr++) {
        int row = row0 + wq + 8 * rr;
        const float4* h4 = (const float4*)(hs + (size_t)row * Hn);
        float acc = 0.f;
        if (act) {
            #pragma unroll 4
            for (int k = 0; k < Hn / 4; k++) {
                float4 a = h4[k]; float4 w = wt4[k];
                acc += a.x * w.x + a.y * w.y + a.z * w.z + a.w * w.w;
            }
        }
        g_text[row * PPn + lane] = act ? acc : 0.f;
        sumsq += acc * acc;

        const float4* a4 = (const float4*)(ad + (size_t)row * FDn);
        float acb = 0.f;
        if (act) {
            #pragma unroll
            for (int k = 0; k < FDn / 4; k++) {
                float4 a = a4[k]; float4 w = wa4[k];
                acb += a.x * w.x + a.y * w.y + a.z * w.z + a.w * w.w;
            }
        }
        g_audio[row * PPn + lane] = act ? acb : 0.f;
    }

    red[tid] = sumsq;
    __syncthreads();
    for (int s = 128; s > 0; s >>= 1) {
        if (tid < s) red[tid] += red[tid + s];
        __syncthreads();
    }
    if (tid == 0) g_part[blockIdx.x] = red[0];
}

// ------------------ K2: finalize norm scale ------------------
__global__ void k_norm() {
    __shared__ float red[512];
    int tid = threadIdx.x;
    red[tid] = g_part[tid];
    __syncthreads();
    for (int s = 256; s > 0; s >>= 1) {
        if (tid < s) red[tid] += red[tid + s];
        __syncthreads();
    }
    if (tid == 0) g_scale[0] = rsqrtf(red[0]);   // 1/norm^2
}

// ------------------ K3: score matrices ------------------
// grid (8 t-tiles, 8 s-tiles, 32 b), block 256 = 16x16, 4x4 microtile.
__global__ __launch_bounds__(256) void k_scores(const float* __restrict__ twp,
                                                const float* __restrict__ awp,
                                                const float* __restrict__ fbp,
                                                float* __restrict__ out_ta,
                                                float* __restrict__ out_fa) {
    __shared__ float sTs[64 * 33], sTt[64 * 33], sAs[64 * 33], sAt[64 * 33];
    int b  = blockIdx.z;
    int s0 = blockIdx.y * 64;
    int t0 = blockIdx.x * 64;
    int tid = threadIdx.x;

    const float* gts = g_text  + (size_t)(b * Sn + s0) * PPn;
    const float* gtt = g_text  + (size_t)(b * Sn + t0) * PPn;
    const float* gas = g_audio + (size_t)(b * Sn + s0) * PPn;
    const float* gat = g_audio + (size_t)(b * Sn + t0) * PPn;
    for (int e = tid; e < 64 * 32; e += 256) {
        int r = e >> 5, p = e & 31;
        sTs[r * 33 + p] = gts[r * 32 + p];
        sTt[r * 33 + p] = gtt[r * 32 + p];
        sAs[r * 33 + p] = gas[r * 32 + p];
        sAt[r * 33 + p] = gat[r * 32 + p];
    }
    __syncthreads();

    int tx = tid & 15, ty = tid >> 4;
    float st[16], sa[16];
    #pragma unroll
    for (int i = 0; i < 16; i++) { st[i] = 0.f; sa[i] = 0.f; }

    const float* ps = sTs + (ty * 4) * 33;
    const float* pt = sTt + (tx * 4) * 33;
    const float* qs = sAs + (ty * 4) * 33;
    const float* qt = sAt + (tx * 4) * 33;

    #pragma unroll 6
    for (int p = 0; p < Pn; p++) {
        float a0 = ps[p], a1 = ps[33 + p], a2 = ps[66 + p], a3 = ps[99 + p];
        float b0 = pt[p], b1 = pt[33 + p], b2 = pt[66 + p], b3 = pt[99 + p];
        st[0]  += a0 * b0; st[1]  += a0 * b1; st[2]  += a0 * b2; st[3]  += a0 * b3;
        st[4]  += a1 * b0; st[5]  += a1 * b1; st[6]  += a1 * b2; st[7]  += a1 * b3;
        st[8]  += a2 * b0; st[9]  += a2 * b1; st[10] += a2 * b2; st[11] += a2 * b3;
        st[12] += a3 * b0; st[13] += a3 * b1; st[14] += a3 * b2; st[15] += a3 * b3;
        float c0 = qs[p], c1 = qs[33 + p], c2 = qs[66 + p], c3 = qs[99 + p];
        float d0 = qt[p], d1 = qt[33 + p], d2 = qt[66 + p], d3 = qt[99 + p];
        sa[0]  += c0 * d0; sa[1]  += c0 * d1; sa[2]  += c0 * d2; sa[3]  += c0 * d3;
        sa[4]  += c1 * d0; sa[5]  += c1 * d1; sa[6]  += c1 * d2; sa[7]  += c1 * d3;
        sa[8]  += c2 * d0; sa[9]  += c2 * d1; sa[10] += c2 * d2; sa[11] += c2 * d3;
        sa[12] += c3 * d0; sa[13] += c3 * d1; sa[14] += c3 * d2; sa[15] += c3 * d3;
    }

    float cs = g_scale[0];
    float tw = twp[0], aw = awp[0], fb = fbp[0];

    #pragma unroll
    for (int i = 0; i < 4; i++) {
        int s = s0 + ty * 4 + i;
        size_t base = ((size_t)(b * Sn + s)) * Sn + t0 + tx * 4;
        float ta[4], fa[4], rw[4];
        #pragma unroll
        for (int j = 0; j < 4; j++) {
            float dt = st[i * 4 + j] * cs;
            float t_ = fmaxf(dt, 0.f);
            float a_ = fmaxf(sa[i * 4 + j], 0.f);
            float r_ = tw * t_ + aw * a_ + fb;
            ta[j] = t_; rw[j] = r_; fa[j] = fmaxf(r_, 0.f);
        }
        *(float4*)(out_ta + base) = make_float4(ta[0], ta[1], ta[2], ta[3]);
        *(float4*)(out_fa + base) = make_float4(fa[0], fa[1], fa[2], fa[3]);
        if (s == 0)
            *(float4*)(g_raw0 + b * Sn + t0 + tx * 4) =
                make_float4(rw[0], rw[1], rw[2], rw[3]);
    }
}

// ------------------ K4: row-0 softmax + att@hidden + residual ------------------
// grid (32, 3), block 256. each block computes 256 h-columns of fusion_data[b,0,:]
__global__ __launch_bounds__(256) void k_attnv(const float* __restrict__ hs,
                                               const float* __restrict__ am) {
    __shared__ float sp[Sn];
    __shared__ float red[256];
    int b = blockIdx.x, hc = blockIdx.y, tid = threadIdx.x;

    float mbase = am[b * Sn];                         // attention_mask[b,0,0,0]
    float l0 = g_raw0[b * Sn + tid]       + am[b * Sn + tid]       + mbase;
    float l1 = g_raw0[b * Sn + tid + 256] + am[b * Sn + tid + 256] + mbase;

    red[tid] = fmaxf(l0, l1);
    __syncthreads();
    for (int s = 128; s > 0; s >>= 1) {
        if (tid < s) red[tid] = fmaxf(red[tid], red[tid + s]);
        __syncthreads();
    }
    float mx = red[0];
    __syncthreads();

    float e0 = expf(l0 - mx), e1 = expf(l1 - mx);
    sp[tid] = e0; sp[tid + 256] = e1;
    red[tid] = e0 + e1;
    __syncthreads();
    for (int s = 128; s > 0; s >>= 1) {
        if (tid < s) red[tid] += red[tid + s];
        __syncthreads();
    }
    float inv = 1.f / red[0];
    __syncthreads();

    int h = hc * 256 + tid;
    const float* hb = hs + (size_t)b * Sn * Hn;
    float acc = 0.f;
    #pragma unroll 4
    for (int t = 0; t < Sn; t++)
        acc += sp[t] * hb[(size_t)t * Hn + h];
    g_fus0[b * Hn + h] = acc * inv + hb[h];            // residual (row 0)
}

// ------------------ K5: dense + layernorm (32 rows) ------------------
__global__ __launch_bounds__(256) void k_dense_ln(const float* __restrict__ Wd,
                                                  const float* __restrict__ bd,
                                                  const float* __restrict__ lw,
                                                  const float* __restrict__ lb,
                                                  float* __restrict__ out0) {
    __shared__ float sx[Hn];
    __shared__ float red[256];
    int b = blockIdx.x, tid = threadIdx.x;
    for (int i = tid; i < Hn; i += 256) sx[i] = g_fus0[b * Hn + i];
    __syncthreads();

    float hv[3];
    #pragma unroll
    for (int j = 0; j < 3; j++) {
        int o = tid + 256 * j;
        const float4* w4 = (const float4*)(Wd + (size_t)o * Hn);
        const float4* x4 = (const float4*)sx;
        float acc = bd[o];
        #pragma unroll 4
        for (int k = 0; k < Hn / 4; k++) {
            float4 w = w4[k]; float4 x = x4[k];
            acc += w.x * x.x + w.y * x.y + w.z * x.z + w.w * x.w;
        }
        hv[j] = acc;
    }

    red[tid] = hv[0] + hv[1] + hv[2];
    __syncthreads();
    for (int s = 128; s > 0; s >>= 1) {
        if (tid < s) red[tid] += red[tid + s];
        __syncthreads();
    }
    float u = red[0] / (float)Hn;
    __syncthreads();

    float vs = 0.f;
    #pragma unroll
    for (int j = 0; j < 3; j++) { float d = hv[j] - u; vs += d * d; }
    red[tid] = vs;
    __syncthreads();
    for (int s = 128; s > 0; s >>= 1) {
        if (tid < s) red[tid] += red[tid + s];
        __syncthreads();
    }
    float rstd = rsqrtf(red[0] / (float)Hn + 1e-12f);
    #pragma unroll
    for (int j = 0; j < 3; j++) {
        int o = tid + 256 * j;
        out0[b * Hn + o] = lw[o] * (hv[j] - u) * rstd + lb[o];
    }
}

// ------------------ launch ------------------
extern "C" void kernel_launch(void* const* d_in, const int* in_sizes, int n_in,
                              void* d_out, int out_size) {
    const float* hs = (const float*)d_in[0];   // hidden_states (32,512,768)
    const float* ad = (const float*)d_in[1];   // audio_data (32,512,64)
    const float* am = (const float*)d_in[2];   // attention_mask (32,1,1,512)
    const float* Wt = (const float*)d_in[3];   // (30,768)
    const float* Wa = (const float*)d_in[4];   // (30,64)
    const float* tw = (const float*)d_in[5];
    const float* aw = (const float*)d_in[6];
    const float* fb = (const float*)d_in[7];
    const float* Wd = (const float*)d_in[8];   // (768,768)
    const float* bd = (const float*)d_in[9];
    const float* lw = (const float*)d_in[10];
    const float* lb = (const float*)d_in[11];

    float* out    = (float*)d_out;
    float* out_h0 = out;                                   // (32,768)
    float* out_ta = out + Bn * Hn;                         // (32,512,512)
    float* out_fa = out + Bn * Hn + (size_t)Bn * Sn * Sn;  // (32,512,512)

    k_proj<<<512, 256>>>(hs, ad, Wt, Wa);
    k_norm<<<1, 512>>>();
    k_scores<<<dim3(8, 8, 32), 256>>>(tw, aw, fb, out_ta, out_fa);
    k_attnv<<<dim3(32, 3), 256>>>(hs, am);
    k_dense_ln<<<32, 256>>>(Wd, bd, lw, lb, out_h0);
}

// round 2
// speedup vs baseline: 5.6908x; 5.6908x over previous
#include <cuda_runtime.h>
#include <math.h>

#define Bn 32
#define Sn 512
#define Hn 768
#define FDn 64
#define Pn 30
#define PPn 32
#define NROWS (Bn*Sn)    // 16384

// ------------------ scratch ------------------
__device__ float g_WT [Hn * PPn];       // W_t transposed [k][p], zero-padded p
__device__ float g_WaT[FDn * PPn];      // W_a transposed [k][p]
__device__ float g_textT [Bn * PPn * Sn];  // [b][p][s]
__device__ float g_audioT[Bn * PPn * Sn];  // [b][p][s]
__device__ float g_part[128];
__device__ float g_scale[1];
__device__ float g_raw0[Bn * Sn];
__device__ float g_prob[Bn * Sn];
__device__ float g_avp[Bn * 16 * Hn];
__device__ float g_h[Bn * Hn];

// ------------------ K0: transpose weights ------------------
__global__ void k_prep(const float* __restrict__ Wt, const float* __restrict__ Wa) {
    int e = blockIdx.x * 256 + threadIdx.x;
    if (blockIdx.x < 96) {                 // 768*32 = 24576
        int p = e & 31, k = e >> 5;
        g_WT[k * 32 + p] = (p < Pn) ? Wt[p * Hn + k] : 0.f;
    } else {
        e -= 96 * 256;                     // 64*32 = 2048
        int p = e & 31, k = e >> 5;
        g_WaT[k * 32 + p] = (p < Pn) ? Wa[p * FDn + k] : 0.f;
    }
}

// ------------------ K1: tiled projection GEMM ------------------
// 128 blocks x 256 threads. Block: 128 rows x 32 p. Thread: 4r x 4p.
#define FSTEP(Ai, i)                                                        \
    acc[i][0] += Ai.x*W0.x + Ai.y*W1.x + Ai.z*W2.x + Ai.w*W3.x;             \
    acc[i][1] += Ai.x*W0.y + Ai.y*W1.y + Ai.z*W2.y + Ai.w*W3.y;             \
    acc[i][2] += Ai.x*W0.z + Ai.y*W1.z + Ai.z*W2.z + Ai.w*W3.z;             \
    acc[i][3] += Ai.x*W0.w + Ai.y*W1.w + Ai.z*W2.w + Ai.w*W3.w;

__global__ __launch_bounds__(256) void k_proj(const float* __restrict__ hs,
                                              const float* __restrict__ ad) {
    __shared__ float sA[128 * 68];
    __shared__ float sW[64 * 36];
    int tid = threadIdx.x;
    int pg = tid & 7, rg = tid >> 3;       // p = pg*4+j, r = rg*4+i
    int row0 = blockIdx.x * 128;
    int b = row0 >> 9, s0 = row0 & 511;

    float acc[4][4];
    #pragma unroll
    for (int i = 0; i < 4; i++)
        #pragma unroll
        for (int j = 0; j < 4; j++) acc[i][j] = 0.f;

    // ---- text: K=768 in 12 chunks of 64 ----
    for (int kc = 0; kc < 12; kc++) {
        __syncthreads();
        #pragma unroll
        for (int q = 0; q < 8; q++) {      // A tile 128x64
            int e = tid + 256 * q;
            int r = e >> 4, c = e & 15;
            float4 v = ((const float4*)hs)[(size_t)(row0 + r) * 192 + kc * 16 + c];
            *(float4*)&sA[r * 68 + c * 4] = v;
        }
        #pragma unroll
        for (int q = 0; q < 2; q++) {      // W tile 64x32
            int e = tid + 256 * q;
            int k = e >> 3, pc = e & 7;
            float4 v = ((const float4*)g_WT)[(kc * 64 + k) * 8 + pc];
            *(float4*)&sW[k * 36 + pc * 4] = v;
        }
        __syncthreads();
        #pragma unroll
        for (int kk = 0; kk < 16; kk++) {
            int k = kk * 4;
            float4 A0 = *(float4*)&sA[(rg * 4 + 0) * 68 + k];
            float4 A1 = *(float4*)&sA[(rg * 4 + 1) * 68 + k];
            float4 A2 = *(float4*)&sA[(rg * 4 + 2) * 68 + k];
            float4 A3 = *(float4*)&sA[(rg * 4 + 3) * 68 + k];
            float4 W0 = *(float4*)&sW[(k + 0) * 36 + pg * 4];
            float4 W1 = *(float4*)&sW[(k + 1) * 36 + pg * 4];
            float4 W2 = *(float4*)&sW[(k + 2) * 36 + pg * 4];
            float4 W3 = *(float4*)&sW[(k + 3) * 36 + pg * 4];
            FSTEP(A0, 0) FSTEP(A1, 1) FSTEP(A2, 2) FSTEP(A3, 3)
        }
    }
    float sumsq = 0.f;
    #pragma unroll
    for (int i = 0; i < 4; i++)
        #pragma unroll
        for (int j = 0; j < 4; j++) {
            sumsq += acc[i][j] * acc[i][j];
            int p = pg * 4 + j, s = s0 + rg * 4 + i;
            g_textT[((size_t)(b * 32 + p)) * 512 + s] = acc[i][j];
        }

    // ---- audio: K=64, one chunk ----
    #pragma unroll
    for (int i = 0; i < 4; i++)
        #pragma unroll
        for (int j = 0; j < 4; j++) acc[i][j] = 0.f;
    __syncthreads();
    #pragma unroll
    for (int q = 0; q < 8; q++) {
        int e = tid + 256 * q;
        int r = e >> 4, c = e & 15;
        float4 v = ((const float4*)ad)[(size_t)(row0 + r) * 16 + c];
        *(float4*)&sA[r * 68 + c * 4] = v;
    }
    #pragma unroll
    for (int q = 0; q < 2; q++) {
        int e = tid + 256 * q;
        int k = e >> 3, pc = e & 7;
        float4 v = ((const float4*)g_WaT)[k * 8 + pc];
        *(float4*)&sW[k * 36 + pc * 4] = v;
    }
    __syncthreads();
    #pragma unroll
    for (int kk = 0; kk < 16; kk++) {
        int k = kk * 4;
        float4 A0 = *(float4*)&sA[(rg * 4 + 0) * 68 + k];
        float4 A1 = *(float4*)&sA[(rg * 4 + 1) * 68 + k];
        float4 A2 = *(float4*)&sA[(rg * 4 + 2) * 68 + k];
        float4 A3 = *(float4*)&sA[(rg * 4 + 3) * 68 + k];
        float4 W0 = *(float4*)&sW[(k + 0) * 36 + pg * 4];
        float4 W1 = *(float4*)&sW[(k + 1) * 36 + pg * 4];
        float4 W2 = *(float4*)&sW[(k + 2) * 36 + pg * 4];
        float4 W3 = *(float4*)&sW[(k + 3) * 36 + pg * 4];
        FSTEP(A0, 0) FSTEP(A1, 1) FSTEP(A2, 2) FSTEP(A3, 3)
    }
    #pragma unroll
    for (int i = 0; i < 4; i++)
        #pragma unroll
        for (int j = 0; j < 4; j++) {
            int p = pg * 4 + j, s = s0 + rg * 4 + i;
            g_audioT[((size_t)(b * 32 + p)) * 512 + s] = acc[i][j];
        }

    // ---- sumsq block reduce (reuse sW) ----
    __syncthreads();
    float* red = sW;
    red[tid] = sumsq;
    __syncthreads();
    for (int s = 128; s > 0; s >>= 1) {
        if (tid < s) red[tid] += red[tid + s];
        __syncthreads();
    }
    if (tid == 0) g_part[blockIdx.x] = red[0];
}

// ------------------ K2: norm scale ------------------
__global__ void k_norm() {
    __shared__ float red[128];
    int tid = threadIdx.x;
    red[tid] = g_part[tid];
    __syncthreads();
    for (int s = 64; s > 0; s >>= 1) {
        if (tid < s) red[tid] += red[tid + s];
        __syncthreads();
    }
    if (tid == 0) g_scale[0] = rsqrtf(red[0]);
}

// ------------------ K3: symmetric score matrices ------------------
// grid (36 upper-tri tile pairs, 32 b), 256 threads, 64x64 tiles, 4x4 micro.
__global__ __launch_bounds__(256) void k_scores(const float* __restrict__ twp,
                                                const float* __restrict__ awp,
                                                const float* __restrict__ fbp,
                                                float* __restrict__ out_ta,
                                                float* __restrict__ out_fa) {
    __shared__ float sTs[32 * 64], sTt[32 * 64], sAs[32 * 64], sAt[32 * 64];
    int x = blockIdx.x, si = 0;
    while (x >= 8 - si) { x -= 8 - si; si++; }
    int ti = si + x;
    int b = blockIdx.y;
    int s0 = si * 64, t0 = ti * 64;
    int tid = threadIdx.x;

    const float4* gT = (const float4*)(g_textT  + (size_t)b * 32 * 512);
    const float4* gA = (const float4*)(g_audioT + (size_t)b * 32 * 512);
    #pragma unroll
    for (int q = 0; q < 2; q++) {
        int e = tid + 256 * q;              // 512 float4 per array
        int p = e >> 4, c = e & 15;
        *(float4*)&sTs[p * 64 + c * 4] = gT[p * 128 + (s0 >> 2) + c];
        *(float4*)&sTt[p * 64 + c * 4] = gT[p * 128 + (t0 >> 2) + c];
        *(float4*)&sAs[p * 64 + c * 4] = gA[p * 128 + (s0 >> 2) + c];
        *(float4*)&sAt[p * 64 + c * 4] = gA[p * 128 + (t0 >> 2) + c];
    }
    __syncthreads();

    int tx = tid & 15, ty = tid >> 4;
    float st[16], sa[16];
    #pragma unroll
    for (int i = 0; i < 16; i++) { st[i] = 0.f; sa[i] = 0.f; }

    #pragma unroll 6
    for (int p = 0; p < Pn; p++) {
        float4 a = *(float4*)&sTs[p * 64 + ty * 4];
        float4 bt = *(float4*)&sTt[p * 64 + tx * 4];
        float4 c = *(float4*)&sAs[p * 64 + ty * 4];
        float4 d = *(float4*)&sAt[p * 64 + tx * 4];
        st[0]  += a.x*bt.x; st[1]  += a.x*bt.y; st[2]  += a.x*bt.z; st[3]  += a.x*bt.w;
        st[4]  += a.y*bt.x; st[5]  += a.y*bt.y; st[6]  += a.y*bt.z; st[7]  += a.y*bt.w;
        st[8]  += a.z*bt.x; st[9]  += a.z*bt.y; st[10] += a.z*bt.z; st[11] += a.z*bt.w;
        st[12] += a.w*bt.x; st[13] += a.w*bt.y; st[14] += a.w*bt.z; st[15] += a.w*bt.w;
        sa[0]  += c.x*d.x;  sa[1]  += c.x*d.y;  sa[2]  += c.x*d.z;  sa[3]  += c.x*d.w;
        sa[4]  += c.y*d.x;  sa[5]  += c.y*d.y;  sa[6]  += c.y*d.z;  sa[7]  += c.y*d.w;
        sa[8]  += c.z*d.x;  sa[9]  += c.z*d.y;  sa[10] += c.z*d.z;  sa[11] += c.z*d.w;
        sa[12] += c.w*d.x;  sa[13] += c.w*d.y;  sa[14] += c.w*d.z;  sa[15] += c.w*d.w;
    }

    float cs = g_scale[0];
    float tw = twp[0], aw = awp[0], fb = fbp[0];
    float ta[16], fa[16];
    float rw[4];
    #pragma unroll
    for (int i = 0; i < 4; i++)
        #pragma unroll
        for (int j = 0; j < 4; j++) {
            float t_ = fmaxf(st[i * 4 + j] * cs, 0.f);
            float a_ = fmaxf(sa[i * 4 + j], 0.f);
            float r_ = tw * t_ + aw * a_ + fb;
            ta[i * 4 + j] = t_;
            fa[i * 4 + j] = fmaxf(r_, 0.f);
            if (i == 0) rw[j] = r_;
        }

    // normal store [s][t]
    #pragma unroll
    for (int i = 0; i < 4; i++) {
        int s = s0 + ty * 4 + i;
        size_t base = ((size_t)(b * Sn + s)) * Sn + t0 + tx * 4;
        *(float4*)(out_ta + base) = make_float4(ta[i*4], ta[i*4+1], ta[i*4+2], ta[i*4+3]);
        *(float4*)(out_fa + base) = make_float4(fa[i*4], fa[i*4+1], fa[i*4+2], fa[i*4+3]);
    }
    if (si == 0 && ty == 0)
        *(float4*)(g_raw0 + b * Sn + t0 + tx * 4) =
            make_float4(rw[0], rw[1], rw[2], rw[3]);

    // mirror store [t][s]
    if (si != ti) {
        #pragma unroll
        for (int j = 0; j < 4; j++) {
            int t = t0 + tx * 4 + j;
            size_t base = ((size_t)(b * Sn + t)) * Sn + s0 + ty * 4;
            *(float4*)(out_ta + base) = make_float4(ta[j], ta[4+j], ta[8+j], ta[12+j]);
            *(float4*)(out_fa + base) = make_float4(fa[j], fa[4+j], fa[8+j], fa[12+j]);
        }
    }
}

// ------------------ K4: softmax probs for s=0 row ------------------
__global__ __launch_bounds__(256) void k_soft(const float* __restrict__ am) {
    __shared__ float red[256];
    int b = blockIdx.x, tid = threadIdx.x;
    float mbase = am[b * Sn];
    float l0 = g_raw0[b * Sn + tid]       + am[b * Sn + tid]       + mbase;
    float l1 = g_raw0[b * Sn + tid + 256] + am[b * Sn + tid + 256] + mbase;

    red[tid] = fmaxf(l0, l1);
    __syncthreads();
    for (int s = 128; s > 0; s >>= 1) {
        if (tid < s) red[tid] = fmaxf(red[tid], red[tid + s]);
        __syncthreads();
    }
    float mx = red[0];
    __syncthreads();
    float e0 = expf(l0 - mx), e1 = expf(l1 - mx);
    red[tid] = e0 + e1;
    __syncthreads();
    for (int s = 128; s > 0; s >>= 1) {
        if (tid < s) red[tid] += red[tid + s];
        __syncthreads();
    }
    float inv = 1.f / red[0];
    g_prob[b * Sn + tid]       = e0 * inv;
    g_prob[b * Sn + tid + 256] = e1 * inv;
}

// ------------------ K5: att @ hidden (t-split partials) ------------------
// grid (32 b, 16 t-chunks), 192 threads (one float4 of h each)
__global__ __launch_bounds__(192) void k_av(const float* __restrict__ hs) {
    __shared__ float sp[32];
    int b = blockIdx.x, cy = blockIdx.y, tid = threadIdx.x;
    int t0 = cy * 32;
    if (tid < 32) sp[tid] = g_prob[b * Sn + t0 + tid];
    __syncthreads();

    const float4* hb = (const float4*)(hs + (size_t)b * Sn * Hn);
    float4 acc = make_float4(0.f, 0.f, 0.f, 0.f);
    #pragma unroll 4
    for (int t = 0; t < 32; t++) {
        float p = sp[t];
        float4 h = hb[(size_t)(t0 + t) * 192 + tid];
        acc.x += p * h.x; acc.y += p * h.y; acc.z += p * h.z; acc.w += p * h.w;
    }
    ((float4*)g_avp)[(size_t)(b * 16 + cy) * 192 + tid] = acc;
}

// ------------------ K6: dense GEMV (split over o) ------------------
// grid (32 b, 8 o-chunks), 256 threads = 8 warps, warp computes 12 outputs
__global__ __launch_bounds__(256) void k_dense(const float* __restrict__ hs,
                                               const float* __restrict__ Wd,
                                               const float* __restrict__ bd) {
    __shared__ float sx[Hn];
    int b = blockIdx.x, oc = blockIdx.y, tid = threadIdx.x;
    int w = tid >> 5, lane = tid & 31;

    for (int i = tid; i < Hn; i += 256) {
        float v = hs[(size_t)b * Sn * Hn + i];
        #pragma unroll
        for (int c = 0; c < 16; c++) v += g_avp[(size_t)(b * 16 + c) * Hn + i];
        sx[i] = v;
    }
    __syncthreads();

    const float4* sx4 = (const float4*)sx;
    #pragma unroll
    for (int q = 0; q < 12; q++) {
        int o = oc * 96 + w * 12 + q;
        const float4* w4 = (const float4*)(Wd + (size_t)o * Hn);
        float acc = 0.f;
        #pragma unroll
        for (int c = 0; c < 6; c++) {
            float4 wv = w4[c * 32 + lane];
            float4 xv = sx4[c * 32 + lane];
            acc += wv.x * xv.x + wv.y * xv.y + wv.z * xv.z + wv.w * xv.w;
        }
        #pragma unroll
        for (int s = 16; s > 0; s >>= 1)
            acc += __shfl_down_sync(0xffffffff, acc, s);
        if (lane == 0) g_h[b * Hn + o] = acc + bd[o];
    }
}

// ------------------ K7: layernorm ------------------
__global__ __launch_bounds__(256) void k_ln(const float* __restrict__ lw,
                                            const float* __restrict__ lb,
                                            float* __restrict__ out0) {
    __shared__ float red[256];
    int b = blockIdx.x, tid = threadIdx.x;
    float hv[3];
    #pragma unroll
    for (int j = 0; j < 3; j++) hv[j] = g_h[b * Hn + tid + 256 * j];

    red[tid] = hv[0] + hv[1] + hv[2];
    __syncthreads();
    for (int s = 128; s > 0; s >>= 1) {
        if (tid < s) red[tid] += red[tid + s];
        __syncthreads();
    }
    float u = red[0] / (float)Hn;
    __syncthreads();
    float vs = 0.f;
    #pragma unroll
    for (int j = 0; j < 3; j++) { float d = hv[j] - u; vs += d * d; }
    red[tid] = vs;
    __syncthreads();
    for (int s = 128; s > 0; s >>= 1) {
        if (tid < s) red[tid] += red[tid + s];
        __syncthreads();
    }
    float rstd = rsqrtf(red[0] / (float)Hn + 1e-12f);
    #pragma unroll
    for (int j = 0; j < 3; j++) {
        int o = tid + 256 * j;
        out0[b * Hn + o] = lw[o] * (hv[j] - u) * rstd + lb[o];
    }
}

// ------------------ launch ------------------
extern "C" void kernel_launch(void* const* d_in, const int* in_sizes, int n_in,
                              void* d_out, int out_size) {
    const float* hs = (const float*)d_in[0];
    const float* ad = (const float*)d_in[1];
    const float* am = (const float*)d_in[2];
    const float* Wt = (const float*)d_in[3];
    const float* Wa = (const float*)d_in[4];
    const float* tw = (const float*)d_in[5];
    const float* aw = (const float*)d_in[6];
    const float* fb = (const float*)d_in[7];
    const float* Wd = (const float*)d_in[8];
    const float* bd = (const float*)d_in[9];
    const float* lw = (const float*)d_in[10];
    const float* lb = (const float*)d_in[11];

    float* out    = (float*)d_out;
    float* out_h0 = out;
    float* out_ta = out + Bn * Hn;
    float* out_fa = out + Bn * Hn + (size_t)Bn * Sn * Sn;

    k_prep<<<104, 256>>>(Wt, Wa);
    k_proj<<<128, 256>>>(hs, ad);
    k_norm<<<1, 128>>>();
    k_scores<<<dim3(36, 32), 256>>>(tw, aw, fb, out_ta, out_fa);
    k_soft<<<32, 256>>>(am);
    k_av<<<dim3(32, 16), 192>>>(hs);
    k_dense<<<dim3(32, 8), 256>>>(hs, Wd, bd);
    k_ln<<<32, 256>>>(lw, lb, out_h0);
}